// round 7
// baseline (speedup 1.0000x reference)
#include <cuda_runtime.h>
#include <cstdint>

#define BATCH 512
#define TLEN  8192
#define DTC   1e-3f
#define TILE  1024             // steps per tile
#define NTILE (TLEN / TILE)    // 8
#define NWARP 16               // warps per block
#define NTHR  (NWARP * 32)     // 512
#define LS    2                // steps per lane

// padded smem index: row = 8 steps + 1 pad slot
__device__ __forceinline__ int sidx(int s) { return (s >> 3) * 9 + (s & 7); }
#define ROWS      (TILE / 8)            // 128
#define SQ_ELEMS  (ROWS * 9)            // 1152 float4
#define SQ_BYTES  (SQ_ELEMS * 16)       // 18432
#define SD_BYTES  (SQ_ELEMS * 8)        // 9216
#define BUF_BYTES (SQ_BYTES + SD_BYTES) // 27648
#define SMEM_BYTES (2 * BUF_BYTES)      // 55296 (dynamic)

__device__ __forceinline__ void cp16(uint32_t dst, const void* src) {
    asm volatile("cp.async.cg.shared.global [%0], [%1], 16;" :: "r"(dst), "l"(src));
}
__device__ __forceinline__ void cp8(uint32_t dst, const void* src) {
    asm volatile("cp.async.ca.shared.global [%0], [%1], 8;" :: "r"(dst), "l"(src));
}
__device__ __forceinline__ void cp_commit() { asm volatile("cp.async.commit_group;"); }
__device__ __forceinline__ void cp_wait0()  { asm volatile("cp.async.wait_group 0;"); }

// self = self ∘ prev (prev applied first)
__device__ __forceinline__ void compose(float& M00, float& M01, float& M10, float& M11,
                                        float& v0, float& v1,
                                        float pM00, float pM01, float pM10, float pM11,
                                        float pv0, float pv1) {
    float n00 = M00 * pM00 + M01 * pM10;
    float n01 = M00 * pM01 + M01 * pM11;
    float n10 = M10 * pM00 + M11 * pM10;
    float n11 = M10 * pM01 + M11 * pM11;
    float nv0 = M00 * pv0 + M01 * pv1 + v0;
    float nv1 = M10 * pv0 + M11 * pv1 + v1;
    M00 = n00; M01 = n01; M10 = n10; M11 = n11; v0 = nv0; v1 = nv1;
}

__device__ __forceinline__ void step_transform(float4 q, float2 d,
                                               float a00, float a01, float a10, float a11,
                                               float c00, float c01, float c10, float c11,
                                               float& T00, float& T01, float& T10, float& T11,
                                               float& b0, float& b1) {
    T00 = 1.0f + DTC * (a00 - (q.x * c00 + q.y * c10));
    T01 =        DTC * (a01 - (q.x * c01 + q.y * c11));
    T10 =        DTC * (a10 - (q.z * c00 + q.w * c10));
    T11 = 1.0f + DTC * (a11 - (q.z * c01 + q.w * c11));
    b0  = q.x * d.x + q.y * d.y;
    b1  = q.z * d.x + q.w * d.y;
}

// ---------------- Fused pipelined kernel: one block (512 thr) per batch row ----------------
__global__ __launch_bounds__(NTHR, 3)
void kFused(const float4* __restrict__ xic, const float2* __restrict__ dyv,
            const float* __restrict__ Ac, const float* __restrict__ Cm,
            float2* __restrict__ out) {
    extern __shared__ char smem[];
    __shared__ float wc[NWARP][6];   // warp composites
    __shared__ float xs[NWARP][2];   // state at start of each warp's segment
    __shared__ float carry[2];       // state carried across tiles

    const int tid  = threadIdx.x;
    const int lane = tid & 31;
    const int w    = tid >> 5;
    const int b    = blockIdx.x;

    const float c00 = __ldg(Cm + 0), c01 = __ldg(Cm + 1), c10 = __ldg(Cm + 2), c11 = __ldg(Cm + 3);
    const float a00 = __ldg(Ac + 0), a01 = __ldg(Ac + 1), a10 = __ldg(Ac + 2), a11 = __ldg(Ac + 3);

    if (tid == 0) { carry[0] = 1.0f; carry[1] = 0.0f; }

    const size_t rowbase = (size_t)b * TLEN;
    const uint32_t smem_u32 = (uint32_t)__cvta_generic_to_shared(smem);

    // stage tile `t` into buffer `buf` via cp.async (per-thread slots s = j*NTHR+tid)
    auto stage = [&](int t, int buf) {
        const uint32_t sq_u = smem_u32 + buf * BUF_BYTES;
        const uint32_t sd_u = sq_u + SQ_BYTES;
        const float4* xp = xic + rowbase + t * TILE;
        const float2* dp = dyv + rowbase + t * TILE;
        #pragma unroll
        for (int j = 0; j < TILE / NTHR; j++) {
            int s = j * NTHR + tid;
            int si = sidx(s);
            cp16(sq_u + si * 16, xp + s);
            cp8(sd_u + si * 8, dp + s);
        }
        cp_commit();
    };

    stage(0, 0);

    for (int tile = 0; tile < NTILE; tile++) {
        const int buf = tile & 1;
        const float4* sq = (const float4*)(smem + buf * BUF_BYTES);
        const float2* sd = (const float2*)(smem + buf * BUF_BYTES + SQ_BYTES);

        cp_wait0();
        __syncthreads();   // sync1: staged data visible

        // --- load this lane's 2 steps, immediately prefetch next tile ---
        const int s0 = w * 64 + lane * 2;
        const int si0 = sidx(s0), si1 = sidx(s0 + 1);
        float4 q0 = sq[si0];
        float2 d0 = sd[si0];
        float4 q1 = sq[si1];
        float2 d1 = sd[si1];

        if (tile + 1 < NTILE) stage(tile + 1, buf ^ 1);   // writes buf^1: safe, its readers done pre-sync1

        // --- per-step transforms (kept in regs for replay) ---
        float T00, T01, T10, T11, B00, B01;   // step 0
        float U00, U01, U10, U11, B10, B11;   // step 1
        step_transform(q0, d0, a00, a01, a10, a11, c00, c01, c10, c11, T00, T01, T10, T11, B00, B01);
        step_transform(q1, d1, a00, a01, a10, a11, c00, c01, c10, c11, U00, U01, U10, U11, B10, B11);

        // lane composite = U ∘ T
        float M00 = U00 * T00 + U01 * T10;
        float M01 = U00 * T01 + U01 * T11;
        float M10 = U10 * T00 + U11 * T10;
        float M11 = U10 * T01 + U11 * T11;
        float v0  = U00 * B00 + U01 * B01 + B10;
        float v1  = U10 * B00 + U11 * B01 + B11;

        // --- warp inclusive scan ---
        #pragma unroll
        for (int d = 1; d < 32; d <<= 1) {
            float pM00 = __shfl_up_sync(0xffffffffu, M00, d);
            float pM01 = __shfl_up_sync(0xffffffffu, M01, d);
            float pM10 = __shfl_up_sync(0xffffffffu, M10, d);
            float pM11 = __shfl_up_sync(0xffffffffu, M11, d);
            float pv0  = __shfl_up_sync(0xffffffffu, v0,  d);
            float pv1  = __shfl_up_sync(0xffffffffu, v1,  d);
            if (lane >= d) compose(M00, M01, M10, M11, v0, v1, pM00, pM01, pM10, pM11, pv0, pv1);
        }

        if (lane == 31) {
            wc[w][0] = M00; wc[w][1] = M01; wc[w][2] = M10;
            wc[w][3] = M11; wc[w][4] = v0;  wc[w][5] = v1;
        }
        __syncthreads();   // sync2: wc ready

        // --- warp 0, lanes 0-15: scan warp composites, derive per-warp start states ---
        if (w == 0 && lane < NWARP) {
            float cx0 = carry[0], cx1 = carry[1];   // read before lane 15 overwrites
            float W00 = wc[lane][0], W01 = wc[lane][1], W10 = wc[lane][2];
            float W11 = wc[lane][3], Wv0 = wc[lane][4], Wv1 = wc[lane][5];
            #pragma unroll
            for (int d = 1; d < NWARP; d <<= 1) {
                float pM00 = __shfl_up_sync(0xffffu, W00, d);
                float pM01 = __shfl_up_sync(0xffffu, W01, d);
                float pM10 = __shfl_up_sync(0xffffu, W10, d);
                float pM11 = __shfl_up_sync(0xffffu, W11, d);
                float pv0  = __shfl_up_sync(0xffffu, Wv0, d);
                float pv1  = __shfl_up_sync(0xffffu, Wv1, d);
                if (lane >= d) compose(W00, W01, W10, W11, Wv0, Wv1, pM00, pM01, pM10, pM11, pv0, pv1);
            }
            // exclusive prefix
            float eM00 = __shfl_up_sync(0xffffu, W00, 1);
            float eM01 = __shfl_up_sync(0xffffu, W01, 1);
            float eM10 = __shfl_up_sync(0xffffu, W10, 1);
            float eM11 = __shfl_up_sync(0xffffu, W11, 1);
            float ev0  = __shfl_up_sync(0xffffu, Wv0, 1);
            float ev1  = __shfl_up_sync(0xffffu, Wv1, 1);
            if (lane == 0) { eM00 = 1.f; eM01 = 0.f; eM10 = 0.f; eM11 = 1.f; ev0 = 0.f; ev1 = 0.f; }

            xs[lane][0] = eM00 * cx0 + eM01 * cx1 + ev0;
            xs[lane][1] = eM10 * cx0 + eM11 * cx1 + ev1;
            if (lane == NWARP - 1) {
                carry[0] = W00 * cx0 + W01 * cx1 + Wv0;
                carry[1] = W10 * cx0 + W11 * cx1 + Wv1;
            }
        }
        __syncthreads();   // sync3: xs/carry ready

        // --- exclusive lane prefix, apply to warp start state ---
        float pM00 = __shfl_up_sync(0xffffffffu, M00, 1);
        float pM01 = __shfl_up_sync(0xffffffffu, M01, 1);
        float pM10 = __shfl_up_sync(0xffffffffu, M10, 1);
        float pM11 = __shfl_up_sync(0xffffffffu, M11, 1);
        float pv0  = __shfl_up_sync(0xffffffffu, v0,  1);
        float pv1  = __shfl_up_sync(0xffffffffu, v1,  1);
        if (lane == 0) { pM00 = 1.f; pM01 = 0.f; pM10 = 0.f; pM11 = 1.f; pv0 = 0.f; pv1 = 0.f; }

        float xw0 = xs[w][0], xw1 = xs[w][1];
        float x0 = pM00 * xw0 + pM01 * xw1 + pv0;
        float x1 = pM10 * xw0 + pM11 * xw1 + pv1;

        // --- replay 2 steps from register transforms; one coalesced float4 store ---
        float4 o;
        o.x = DTC * (c00 * x0 + c01 * x1);
        o.y = DTC * (c10 * x0 + c11 * x1);
        {
            float nx0 = T00 * x0 + T01 * x1 + B00;
            float nx1 = T10 * x0 + T11 * x1 + B01;
            x0 = nx0; x1 = nx1;
        }
        o.z = DTC * (c00 * x0 + c01 * x1);
        o.w = DTC * (c10 * x0 + c11 * x1);

        float4* op = (float4*)(out + rowbase + tile * TILE + s0);
        *op = o;
        // no trailing sync: replay touched no smem; buf is next written by
        // stage(tile+2), which is behind sync1(tile+1) -> all reads complete.
    }
}

extern "C" void kernel_launch(void* const* d_in, const int* in_sizes, int n_in,
                              void* d_out, int out_size) {
    const float4* xic = (const float4*)d_in[0];   // [B,T,2,2] f32
    const float2* dyv = (const float2*)d_in[1];   // [B,T,2]   f32
    const float*  Ac  = (const float*)d_in[2];    // [2,2]
    const float*  Cm  = (const float*)d_in[3];    // [2,2]
    float2* out = (float2*)d_out;                 // [B,T,2]

    cudaFuncSetAttribute(kFused, cudaFuncAttributeMaxDynamicSharedMemorySize, SMEM_BYTES);
    kFused<<<BATCH, NTHR, SMEM_BYTES>>>(xic, dyv, Ac, Cm, out);
}

// round 8
// speedup vs baseline: 1.3167x; 1.3167x over previous
#include <cuda_runtime.h>
#include <cstdint>

#define BATCH 512
#define TLEN  8192
#define DTC   1e-3f
#define NWARP 8
#define NTHR  (NWARP * 32)     // 256
#define LS    2                // steps per lane
#define TILE  (NTHR * LS)      // 512
#define NTILE (TLEN / TILE)    // 16

// self = self ∘ prev (prev applied first)
__device__ __forceinline__ void compose(float& M00, float& M01, float& M10, float& M11,
                                        float& v0, float& v1,
                                        float pM00, float pM01, float pM10, float pM11,
                                        float pv0, float pv1) {
    float n00 = M00 * pM00 + M01 * pM10;
    float n01 = M00 * pM01 + M01 * pM11;
    float n10 = M10 * pM00 + M11 * pM10;
    float n11 = M10 * pM01 + M11 * pM11;
    float nv0 = M00 * pv0 + M01 * pv1 + v0;
    float nv1 = M10 * pv0 + M11 * pv1 + v1;
    M00 = n00; M01 = n01; M10 = n10; M11 = n11; v0 = nv0; v1 = nv1;
}

__device__ __forceinline__ void step_transform(float4 q, float dx, float dy_,
                                               float a00, float a01, float a10, float a11,
                                               float c00, float c01, float c10, float c11,
                                               float& T00, float& T01, float& T10, float& T11,
                                               float& b0, float& b1) {
    T00 = 1.0f + DTC * (a00 - (q.x * c00 + q.y * c10));
    T01 =        DTC * (a01 - (q.x * c01 + q.y * c11));
    T10 =        DTC * (a10 - (q.z * c00 + q.w * c10));
    T11 = 1.0f + DTC * (a11 - (q.z * c01 + q.w * c11));
    b0  = q.x * dx + q.y * dy_;
    b1  = q.z * dx + q.w * dy_;
}

// ---------------- Fused direct-load kernel: one block (256 thr) per batch row ----------------
__global__ __launch_bounds__(NTHR, 4)
void kFused(const float4* __restrict__ xic, const float4* __restrict__ dyv4,
            const float* __restrict__ Ac, const float* __restrict__ Cm,
            float4* __restrict__ out4) {
    __shared__ float wc[NWARP][6];   // warp composites
    __shared__ float xs[NWARP][2];   // state at start of each warp's segment
    __shared__ float carry[2];       // state carried across tiles

    const int tid  = threadIdx.x;
    const int lane = tid & 31;
    const int w    = tid >> 5;
    const int b    = blockIdx.x;

    const float c00 = __ldg(Cm + 0), c01 = __ldg(Cm + 1), c10 = __ldg(Cm + 2), c11 = __ldg(Cm + 3);
    const float a00 = __ldg(Ac + 0), a01 = __ldg(Ac + 1), a10 = __ldg(Ac + 2), a11 = __ldg(Ac + 3);

    if (tid == 0) { carry[0] = 1.0f; carry[1] = 0.0f; }

    const size_t rowbase = (size_t)b * TLEN;
    const int s0 = w * 64 + lane * 2;             // this thread's first step within a tile

    const float4* xp = xic  + rowbase + s0;       // per-thread base, advance by TILE
    const float4* dp = dyv4 + (rowbase >> 1) + (s0 >> 1);
    float4*       op = out4 + (rowbase >> 1) + (s0 >> 1);

    // prologue: load tile 0
    float4 q0  = __ldg(xp);
    float4 q1  = __ldg(xp + 1);
    float4 d01 = __ldg(dp);                       // (d0.x, d0.y, d1.x, d1.y)

    for (int tile = 0; tile < NTILE; tile++) {
        // --- transforms for this tile (consume q0,q1,d01) ---
        float T00, T01, T10, T11, B00, B01;       // step 0
        float U00, U01, U10, U11, B10, B11;       // step 1
        step_transform(q0, d01.x, d01.y, a00, a01, a10, a11, c00, c01, c10, c11,
                       T00, T01, T10, T11, B00, B01);
        step_transform(q1, d01.z, d01.w, a00, a01, a10, a11, c00, c01, c10, c11,
                       U00, U01, U10, U11, B10, B11);

        // --- prefetch next tile into the now-dead registers (overlaps scan+barriers) ---
        if (tile + 1 < NTILE) {
            const float4* xn = xp + (tile + 1) * TILE;
            const float4* dn = dp + (tile + 1) * (TILE / 2);
            q0  = __ldg(xn);
            q1  = __ldg(xn + 1);
            d01 = __ldg(dn);
        }

        // lane composite = U ∘ T
        float M00 = U00 * T00 + U01 * T10;
        float M01 = U00 * T01 + U01 * T11;
        float M10 = U10 * T00 + U11 * T10;
        float M11 = U10 * T01 + U11 * T11;
        float v0  = U00 * B00 + U01 * B01 + B10;
        float v1  = U10 * B00 + U11 * B01 + B11;

        // --- warp inclusive scan ---
        #pragma unroll
        for (int d = 1; d < 32; d <<= 1) {
            float pM00 = __shfl_up_sync(0xffffffffu, M00, d);
            float pM01 = __shfl_up_sync(0xffffffffu, M01, d);
            float pM10 = __shfl_up_sync(0xffffffffu, M10, d);
            float pM11 = __shfl_up_sync(0xffffffffu, M11, d);
            float pv0  = __shfl_up_sync(0xffffffffu, v0,  d);
            float pv1  = __shfl_up_sync(0xffffffffu, v1,  d);
            if (lane >= d) compose(M00, M01, M10, M11, v0, v1, pM00, pM01, pM10, pM11, pv0, pv1);
        }

        if (lane == 31) {
            wc[w][0] = M00; wc[w][1] = M01; wc[w][2] = M10;
            wc[w][3] = M11; wc[w][4] = v0;  wc[w][5] = v1;
        }
        __syncthreads();   // sync A: wc ready

        // --- warp 0, lanes 0-7: scan warp composites, derive per-warp start states ---
        if (w == 0 && lane < NWARP) {
            float cx0 = carry[0], cx1 = carry[1];
            float W00 = wc[lane][0], W01 = wc[lane][1], W10 = wc[lane][2];
            float W11 = wc[lane][3], Wv0 = wc[lane][4], Wv1 = wc[lane][5];
            #pragma unroll
            for (int d = 1; d < NWARP; d <<= 1) {
                float pM00 = __shfl_up_sync(0xffu, W00, d);
                float pM01 = __shfl_up_sync(0xffu, W01, d);
                float pM10 = __shfl_up_sync(0xffu, W10, d);
                float pM11 = __shfl_up_sync(0xffu, W11, d);
                float pv0  = __shfl_up_sync(0xffu, Wv0, d);
                float pv1  = __shfl_up_sync(0xffu, Wv1, d);
                if (lane >= d) compose(W00, W01, W10, W11, Wv0, Wv1, pM00, pM01, pM10, pM11, pv0, pv1);
            }
            // exclusive prefix applied to the carry
            float eM00 = __shfl_up_sync(0xffu, W00, 1);
            float eM01 = __shfl_up_sync(0xffu, W01, 1);
            float eM10 = __shfl_up_sync(0xffu, W10, 1);
            float eM11 = __shfl_up_sync(0xffu, W11, 1);
            float ev0  = __shfl_up_sync(0xffu, Wv0, 1);
            float ev1  = __shfl_up_sync(0xffu, Wv1, 1);
            if (lane == 0) { eM00 = 1.f; eM01 = 0.f; eM10 = 0.f; eM11 = 1.f; ev0 = 0.f; ev1 = 0.f; }

            xs[lane][0] = eM00 * cx0 + eM01 * cx1 + ev0;
            xs[lane][1] = eM10 * cx0 + eM11 * cx1 + ev1;
            if (lane == NWARP - 1) {
                carry[0] = W00 * cx0 + W01 * cx1 + Wv0;
                carry[1] = W10 * cx0 + W11 * cx1 + Wv1;
            }
        }
        __syncthreads();   // sync B: xs/carry ready

        // --- exclusive lane prefix, apply to warp start state ---
        float pM00 = __shfl_up_sync(0xffffffffu, M00, 1);
        float pM01 = __shfl_up_sync(0xffffffffu, M01, 1);
        float pM10 = __shfl_up_sync(0xffffffffu, M10, 1);
        float pM11 = __shfl_up_sync(0xffffffffu, M11, 1);
        float pv0  = __shfl_up_sync(0xffffffffu, v0,  1);
        float pv1  = __shfl_up_sync(0xffffffffu, v1,  1);
        if (lane == 0) { pM00 = 1.f; pM01 = 0.f; pM10 = 0.f; pM11 = 1.f; pv0 = 0.f; pv1 = 0.f; }

        float xw0 = xs[w][0], xw1 = xs[w][1];
        float x0 = pM00 * xw0 + pM01 * xw1 + pv0;
        float x1 = pM10 * xw0 + pM11 * xw1 + pv1;

        // --- replay 2 steps from register transforms; one coalesced float4 store ---
        float4 o;
        o.x = DTC * (c00 * x0 + c01 * x1);
        o.y = DTC * (c10 * x0 + c11 * x1);
        {
            float nx0 = T00 * x0 + T01 * x1 + B00;
            float nx1 = T10 * x0 + T11 * x1 + B01;
            x0 = nx0; x1 = nx1;
        }
        o.z = DTC * (c00 * x0 + c01 * x1);
        o.w = DTC * (c10 * x0 + c11 * x1);

        op[tile * (TILE / 2)] = o;
    }
}

extern "C" void kernel_launch(void* const* d_in, const int* in_sizes, int n_in,
                              void* d_out, int out_size) {
    const float4* xic  = (const float4*)d_in[0];  // [B,T,2,2] f32
    const float4* dyv4 = (const float4*)d_in[1];  // [B,T,2]   f32, viewed as float4 pairs
    const float*  Ac   = (const float*)d_in[2];   // [2,2]
    const float*  Cm   = (const float*)d_in[3];   // [2,2]
    float4* out4 = (float4*)d_out;                // [B,T,2] viewed as float4 pairs

    kFused<<<BATCH, NTHR>>>(xic, dyv4, Ac, Cm, out4);
}